// round 10
// baseline (speedup 1.0000x reference)
#include <cuda_runtime.h>
#include <cuda_fp16.h>
#include <cstdint>

#define B_ROWS 8192
#define D_IN   768
#define D_LAT  12288
#define K_TOP  64
#define K_CAND 96
#define TKBUF  1024

// ---------------- device scratch (no runtime allocation allowed) -----------
__device__ __half    g_Xh[(size_t)B_ROWS * D_IN];
__device__ __half    g_WhT[(size_t)D_LAT * D_IN];
__device__ float     g_WT[(size_t)D_LAT * D_IN];
__device__ uint16_t  g_Hk[(size_t)B_ROWS * D_LAT];   // 16-bit ordered keys of approx H
__device__ int       g_candi[(size_t)B_ROWS * K_CAND];

// ---------------- PTX helpers (compute_103-safe: no tcgen05) ---------------
__device__ __forceinline__ uint32_t smem_u32(const void* p) {
    uint32_t a;
    asm("{ .reg .u64 t; cvta.to.shared.u64 t, %1; cvt.u32.u64 %0, t; }" : "=r"(a) : "l"(p));
    return a;
}
#define CP_ASYNC16(dst, src) \
    asm volatile("cp.async.cg.shared.global [%0], [%1], 16;" :: "r"(dst), "l"(src))
#define CP_COMMIT() asm volatile("cp.async.commit_group;" ::: "memory")
#define CP_WAIT0()  asm volatile("cp.async.wait_group 0;" ::: "memory")

#define LDSM_X4(r0, r1, r2, r3, a) \
    asm volatile("ldmatrix.sync.aligned.m8n8.x4.shared.b16 {%0,%1,%2,%3}, [%4];" \
                 : "=r"(r0), "=r"(r1), "=r"(r2), "=r"(r3) : "r"(a))

// fp16 inputs, fp16 accumulator (half the acc registers of f32-acc)
__device__ __forceinline__ void mma16816_f16(uint32_t* c, const uint32_t* a, const uint32_t* b) {
    asm volatile(
        "mma.sync.aligned.m16n8k16.row.col.f16.f16.f16.f16 "
        "{%0,%1}, {%2,%3,%4,%5}, {%6,%7}, {%0,%1};"
        : "+r"(c[0]), "+r"(c[1])
        : "r"(a[0]), "r"(a[1]), "r"(a[2]), "r"(a[3]), "r"(b[0]), "r"(b[1]));
}

// monotonic fp16 -> u16 key (bigger float => bigger key)
__device__ __forceinline__ uint16_t f2key16(float v) {
    uint16_t u = __half_as_ushort(__float2half(v));
    return (u & 0x8000) ? (uint16_t)~u : (uint16_t)(u | 0x8000);
}

// ---------------------------------------------------------------------------
// Prep kernels: X -> fp16 ; W_enc -> transposed fp32 + fp16 ; nop (profiling
// alignment: keeps the GEMM on the op index ncu captures).
// ---------------------------------------------------------------------------
__global__ void convert_x_kernel(const float* __restrict__ X) {
    const size_t n = (size_t)B_ROWS * D_IN / 2;
    const float2* X2 = reinterpret_cast<const float2*>(X);
    __half2* Y = reinterpret_cast<__half2*>(g_Xh);
    for (size_t i = (size_t)blockIdx.x * blockDim.x + threadIdx.x; i < n;
         i += (size_t)gridDim.x * blockDim.x) {
        float2 v = X2[i];
        Y[i] = __floats2half2_rn(v.x, v.y);
    }
}

__global__ void transpose_w_kernel(const float* __restrict__ W) {
    __shared__ float t[32][33];
    const int bx = blockIdx.x;  // over D_LAT/32
    const int by = blockIdx.y;  // over D_IN/32
    const int tx = threadIdx.x, ty = threadIdx.y;
    #pragma unroll
    for (int i = ty; i < 32; i += 8)
        t[i][tx] = W[(size_t)(by * 32 + i) * D_LAT + bx * 32 + tx];
    __syncthreads();
    #pragma unroll
    for (int i = ty; i < 32; i += 8) {
        float v = t[tx][i];
        size_t o = (size_t)(bx * 32 + i) * D_IN + by * 32 + tx;
        g_WT[o]  = v;
        g_WhT[o] = __float2half(v);
    }
}

__global__ void nop_kernel() {}

// ---------------------------------------------------------------------------
// Kernel: H ~= X @ W_enc + b_enc via fp16 mma.sync (f16 acc); epilogue stores
// u16 ordered keys. 128x128 block tile, 8 warps (64x32 warp tile), BK=64,
// 2-stage cp.async. Rows padded to 144B -> conflict-free ldmatrix.
// f16 acc halves accumulator registers -> 3 CTAs/SM (24 warps).
// ---------------------------------------------------------------------------
#define BKC    64
#define NCH    (D_IN / BKC)          // 12
#define ROWB   144                   // 128B data + 16B pad
#define TILEB  (128 * ROWB)          // 18432 B per operand tile
#define GEMM_DSMEM (4 * TILEB)       // A0 A1 B0 B1 = 73728 B

__global__ __launch_bounds__(256, 3)
void gemm_enc_f16(const float* __restrict__ bias)
{
    extern __shared__ __align__(16) char sraw[];

    const uint32_t sbase = smem_u32(sraw);
    const int tid    = threadIdx.x;
    const int wid    = tid >> 5;
    const int lane   = tid & 31;
    const int warp_m = wid >> 2;          // 0..1
    const int warp_n = wid & 3;           // 0..3
    const int row0   = blockIdx.y * 128;
    const int col0   = blockIdx.x * 128;

    const char* Agl = reinterpret_cast<const char*>(g_Xh);
    const char* Bgl = reinterpret_cast<const char*>(g_WhT);

    // per chunk: 1024 16B-units per operand; 4 per thread per operand
    auto load_chunk = [&](int kc, int buf) {
        #pragma unroll
        for (int t = 0; t < 4; t++) {
            int u   = tid + t * 256;       // 0..1023
            int r   = u >> 3;
            int c16 = u & 7;
            uint32_t da = sbase + buf * TILEB + r * ROWB + c16 * 16;
            const char* sa = Agl + ((size_t)(row0 + r) * D_IN + kc * BKC) * 2 + c16 * 16;
            CP_ASYNC16(da, sa);
            uint32_t db = sbase + (2 + buf) * TILEB + r * ROWB + c16 * 16;
            const char* sb = Bgl + ((size_t)(col0 + r) * D_IN + kc * BKC) * 2 + c16 * 16;
            CP_ASYNC16(db, sb);
        }
    };

    uint32_t acc[4][4][2];               // f16x2 accumulators
    #pragma unroll
    for (int i = 0; i < 4; i++)
        #pragma unroll
        for (int j = 0; j < 4; j++) { acc[i][j][0] = 0u; acc[i][j][1] = 0u; }

    // A ldmatrix lane mapping (x4: 16x16 tile)
    const int a_row = warp_m * 64 + (lane & 15);
    const int a_col = (lane >> 4) * 8;                 // fp16 units
    // B ldmatrix x4 lane mapping: lane groups of 8 -> (nj parity, k half)
    const int bg  = lane >> 3;           // 0..3
    const int blr = lane & 7;
    const int b_rowx = warp_n * 32 + (bg >> 1) * 8 + blr;   // + pj*16
    const int b_colx = (bg & 1) * 8;                         // + ks*16

    load_chunk(0, 0);
    CP_COMMIT();
    CP_WAIT0();
    __syncthreads();

    for (int c = 0; c < NCH; c++) {
        const int buf = c & 1;
        if (c + 1 < NCH) {
            load_chunk(c + 1, buf ^ 1);
            CP_COMMIT();
        }

        const uint32_t sa = sbase + buf * TILEB;
        const uint32_t sb = sbase + (2 + buf) * TILEB;
        #pragma unroll
        for (int ks = 0; ks < 4; ks++) {
            uint32_t af[4][4], bfr[4][2];
            #pragma unroll
            for (int mi = 0; mi < 4; mi++) {
                uint32_t addr = sa + (a_row + mi * 16) * ROWB + (a_col + ks * 16) * 2;
                LDSM_X4(af[mi][0], af[mi][1], af[mi][2], af[mi][3], addr);
            }
            #pragma unroll
            for (int pj = 0; pj < 2; pj++) {
                uint32_t addr = sb + (b_rowx + pj * 16) * ROWB + (b_colx + ks * 16) * 2;
                LDSM_X4(bfr[2 * pj][0], bfr[2 * pj][1],
                        bfr[2 * pj + 1][0], bfr[2 * pj + 1][1], addr);
            }
            #pragma unroll
            for (int mi = 0; mi < 4; mi++)
                #pragma unroll
                for (int nj = 0; nj < 4; nj++)
                    mma16816_f16(acc[mi][nj], af[mi], bfr[nj]);
        }

        if (c + 1 < NCH) {
            CP_WAIT0();
            __syncthreads();
        }
    }

    // epilogue: add bias (fp32), quantize to ordered u16 keys, store pairs
    const int er = lane >> 2;          // 0..7
    const int ec = (lane & 3) * 2;     // 0,2,4,6
    #pragma unroll
    for (int mi = 0; mi < 4; mi++) {
        #pragma unroll
        for (int nj = 0; nj < 4; nj++) {
            const int r  = row0 + warp_m * 64 + mi * 16 + er;
            const int cc = col0 + warp_n * 32 + nj * 8 + ec;
            const float bx = bias[cc], by = bias[cc + 1];
            __half2 h0 = *reinterpret_cast<__half2*>(&acc[mi][nj][0]);
            __half2 h1 = *reinterpret_cast<__half2*>(&acc[mi][nj][1]);
            uint32_t p0 = (uint32_t)f2key16(__low2float(h0) + bx) |
                          ((uint32_t)f2key16(__high2float(h0) + by) << 16);
            uint32_t p1 = (uint32_t)f2key16(__low2float(h1) + bx) |
                          ((uint32_t)f2key16(__high2float(h1) + by) << 16);
            *reinterpret_cast<uint32_t*>(g_Hk + (size_t)r * D_LAT + cc) = p0;
            *reinterpret_cast<uint32_t*>(g_Hk + (size_t)(r + 8) * D_LAT + cc) = p1;
        }
    }
}

// ---------------------------------------------------------------------------
// Kernel: per-row top-96 candidate indices from u16 keys. (R8 structure;
// fp16 keys put 2 mantissa bits in the hi byte -> tiny threshold bucket.)
// ---------------------------------------------------------------------------
__device__ __forceinline__ void hadd(int* hist, int bucket) {
    unsigned m = __match_any_sync(0xffffffffu, bucket);
    if ((threadIdx.x & 31) == __ffs(m) - 1)
        atomicAdd(&hist[bucket], __popc(m));
}

__global__ __launch_bounds__(256)
void topk_kernel()
{
    __shared__ __align__(16) uint32_t skeys[D_LAT / 2];   // 24 KB
    __shared__ int hist[256];
    __shared__ uint32_t buf[TKBUF];                        // (key16<<16)|idx
    __shared__ int s_d1, s_rem1, s_e, s_rem2, s_cnt, s_eq, s_bcnt;

    const int row = blockIdx.x;
    const int tid = threadIdx.x;

    hist[tid] = 0;
    if (tid == 0) { s_cnt = 0; s_eq = 0; s_bcnt = 0; }
    __syncthreads();

    // sweep 1: load -> stage + pass-1 histogram of high bytes (convergent)
    const uint4* src = reinterpret_cast<const uint4*>(g_Hk + (size_t)row * D_LAT);
    uint4* dst = reinterpret_cast<uint4*>(skeys);
    #pragma unroll
    for (int j = 0; j < 6; j++) {
        uint4 v = src[tid + 256 * j];
        dst[tid + 256 * j] = v;
        hadd(hist, (int)((v.x >> 8) & 0xFF));  hadd(hist, (int)(v.x >> 24));
        hadd(hist, (int)((v.y >> 8) & 0xFF));  hadd(hist, (int)(v.y >> 24));
        hadd(hist, (int)((v.z >> 8) & 0xFF));  hadd(hist, (int)(v.z >> 24));
        hadd(hist, (int)((v.w >> 8) & 0xFF));  hadd(hist, (int)(v.w >> 24));
    }
    __syncthreads();
    if (tid == 0) {
        int cum = 0, d = 255;
        for (; d > 0; d--) {
            if (cum + hist[d] >= K_CAND) break;
            cum += hist[d];
        }
        s_d1 = d;
        s_rem1 = K_CAND - cum;
    }
    __syncthreads();
    const int d1 = s_d1, rem1 = s_rem1;
    hist[tid] = 0;
    __syncthreads();

    // sweep 2: classify. definite candidates out; threshold bucket -> buffer
    int* cand = g_candi + (size_t)row * K_CAND;
    #pragma unroll 4
    for (int i = tid; i < D_LAT / 2; i += 256) {
        uint32_t w = skeys[i];
        uint32_t k0 = w & 0xFFFFu, k1 = w >> 16;
        int hb0 = (int)(k0 >> 8), hb1 = (int)(k1 >> 8);
        if (hb0 > d1)       cand[atomicAdd(&s_cnt, 1)] = 2 * i;
        else if (hb0 == d1) {
            int p = atomicAdd(&s_bcnt, 1);
            if (p < TKBUF) buf[p] = (k0 << 16) | (uint32_t)(2 * i);
        }
        if (hb1 > d1)       cand[atomicAdd(&s_cnt, 1)] = 2 * i + 1;
        else if (hb1 == d1) {
            int p = atomicAdd(&s_bcnt, 1);
            if (p < TKBUF) buf[p] = (k1 << 16) | (uint32_t)(2 * i + 1);
        }
    }
    __syncthreads();
    const int bn = s_bcnt;

    if (bn <= TKBUF) {
        for (int i = tid; i < bn; i += 256)
            atomicAdd(&hist[(buf[i] >> 16) & 0xFF], 1);
        __syncthreads();
        if (tid == 0) {
            int cum = 0, e = 255;
            for (; e > 0; e--) {
                if (cum + hist[e] >= rem1) break;
                cum += hist[e];
            }
            s_e = e;
            s_rem2 = rem1 - cum;
        }
        __syncthreads();
        const int e = s_e, rem2 = s_rem2;
        for (int i = tid; i < bn; i += 256) {
            uint32_t w  = buf[i];
            int lb = (int)((w >> 16) & 0xFF);
            if (lb > e)        cand[atomicAdd(&s_cnt, 1)] = (int)(w & 0xFFFFu);
            else if (lb == e && atomicAdd(&s_eq, 1) < rem2)
                               cand[atomicAdd(&s_cnt, 1)] = (int)(w & 0xFFFFu);
        }
    } else {
        // exact fallback (data-independent correctness)
        #pragma unroll 4
        for (int i = tid; i < D_LAT / 2; i += 256) {
            uint32_t w = skeys[i];
            uint32_t k0 = w & 0xFFFFu, k1 = w >> 16;
            if ((int)(k0 >> 8) == d1) atomicAdd(&hist[k0 & 0xFF], 1);
            if ((int)(k1 >> 8) == d1) atomicAdd(&hist[k1 & 0xFF], 1);
        }
        __syncthreads();
        if (tid == 0) {
            int cum = 0, e = 255;
            for (; e > 0; e--) {
                if (cum + hist[e] >= rem1) break;
                cum += hist[e];
            }
            s_e = e;
            s_rem2 = rem1 - cum;
        }
        __syncthreads();
        const int e = s_e, rem2 = s_rem2;
        #pragma unroll 4
        for (int i = tid; i < D_LAT / 2; i += 256) {
            uint32_t w = skeys[i];
            uint32_t k0 = w & 0xFFFFu, k1 = w >> 16;
            if ((int)(k0 >> 8) == d1) {
                int lb = (int)(k0 & 0xFF);
                if (lb > e)        cand[atomicAdd(&s_cnt, 1)] = 2 * i;
                else if (lb == e && atomicAdd(&s_eq, 1) < rem2)
                                   cand[atomicAdd(&s_cnt, 1)] = 2 * i;
            }
            if ((int)(k1 >> 8) == d1) {
                int lb = (int)(k1 & 0xFF);
                if (lb > e)        cand[atomicAdd(&s_cnt, 1)] = 2 * i + 1;
                else if (lb == e && atomicAdd(&s_eq, 1) < rem2)
                                   cand[atomicAdd(&s_cnt, 1)] = 2 * i + 1;
            }
        }
    }
}

// ---------------------------------------------------------------------------
// Kernel: fused exact recompute (fp32) of the 96 candidates + exact top-64
// (jax tie semantics: value desc, index asc) + z scatter + sparse decode.
// ---------------------------------------------------------------------------
__global__ __launch_bounds__(256)
void recon_kernel(const float* __restrict__ X, const float* __restrict__ b_enc,
                  const float* __restrict__ Wdec, const float* __restrict__ bdec,
                  float* __restrict__ z, float* __restrict__ recon)
{
    __shared__ __align__(16) float xs[D_IN];
    __shared__ int   ci[K_CAND];
    __shared__ float cv[K_CAND];
    __shared__ float sv[K_TOP];
    __shared__ int   si[K_TOP];

    const int row = blockIdx.x;
    const int tid = threadIdx.x;
    const int wid = tid >> 5, lane = tid & 31;

    {
        const float4* X4 = reinterpret_cast<const float4*>(X + (size_t)row * D_IN);
        float4* xs4 = reinterpret_cast<float4*>(xs);
        if (tid < D_IN / 4) xs4[tid] = X4[tid];
    }
    if (tid < K_CAND)
        ci[tid] = g_candi[(size_t)row * K_CAND + tid];
    __syncthreads();

    const float4* xs4 = reinterpret_cast<const float4*>(xs);
    for (int c = wid; c < K_CAND; c += 8) {
        const float4* wr = reinterpret_cast<const float4*>(g_WT + (size_t)ci[c] * D_IN);
        float s = 0.f;
        #pragma unroll
        for (int j = 0; j < D_IN / 128; j++) {
            float4 a = xs4[lane + 32 * j];
            float4 b = wr[lane + 32 * j];
            s = fmaf(a.x, b.x, s); s = fmaf(a.y, b.y, s);
            s = fmaf(a.z, b.z, s); s = fmaf(a.w, b.w, s);
        }
        #pragma unroll
        for (int o = 16; o; o >>= 1) s += __shfl_xor_sync(0xffffffff, s, o);
        if (lane == 0) cv[c] = s + b_enc[ci[c]];
    }
    __syncthreads();

    if (tid < K_CAND) {
        const float v  = cv[tid];
        const int   id = ci[tid];
        int r = 0;
        #pragma unroll 8
        for (int j = 0; j < K_CAND; j++) {
            float vj = cv[j];
            r += (vj > v) || (vj == v && ci[j] < id);
        }
        if (r < K_TOP) {
            z[(size_t)row * D_LAT + id] = v;
            sv[r] = v;
            si[r] = id;
        }
    }
    __syncthreads();

    if (tid < D_IN / 4) {
        const float4* W4 = reinterpret_cast<const float4*>(Wdec);
        float4 acc = reinterpret_cast<const float4*>(bdec)[tid];
        #pragma unroll 4
        for (int j = 0; j < K_TOP; j++) {
            float4 w = W4[(size_t)si[j] * (D_IN / 4) + tid];
            float v  = sv[j];
            acc.x = fmaf(v, w.x, acc.x);
            acc.y = fmaf(v, w.y, acc.y);
            acc.z = fmaf(v, w.z, acc.z);
            acc.w = fmaf(v, w.w, acc.w);
        }
        reinterpret_cast<float4*>(recon)[(size_t)row * (D_IN / 4) + tid] = acc;
    }
}

// ---------------------------------------------------------------------------
extern "C" void kernel_launch(void* const* d_in, const int* in_sizes, int n_in,
                              void* d_out, int out_size)
{
    const float* x     = (const float*)d_in[0];
    const float* W_enc = (const float*)d_in[1];
    const float* b_enc = (const float*)d_in[2];
    const float* W_dec = (const float*)d_in[3];
    const float* b_dec = (const float*)d_in[4];

    float* out   = (float*)d_out;
    float* recon = out;                              // [B_ROWS, D_IN]
    float* z     = out + (size_t)B_ROWS * D_IN;      // [B_ROWS, D_LAT]

    cudaFuncSetAttribute(gemm_enc_f16, cudaFuncAttributeMaxDynamicSharedMemorySize,
                         GEMM_DSMEM);

    cudaMemsetAsync(z, 0, (size_t)B_ROWS * D_LAT * sizeof(float));

    convert_x_kernel<<<2048, 256>>>(x);
    transpose_w_kernel<<<dim3(D_LAT / 32, D_IN / 32), dim3(32, 8)>>>(W_enc);

    nop_kernel<<<1, 32>>>();   // keeps GEMM on ncu's captured op index

    gemm_enc_f16<<<dim3(D_LAT / 128, B_ROWS / 128), 256, GEMM_DSMEM>>>(b_enc);

    topk_kernel<<<B_ROWS, 256>>>();
    recon_kernel<<<B_ROWS, 256>>>(x, b_enc, W_dec, b_dec, z, recon);
}

// round 11
// speedup vs baseline: 1.2203x; 1.2203x over previous
#include <cuda_runtime.h>
#include <cuda_fp16.h>
#include <cuda_bf16.h>
#include <cstdint>

#define B_ROWS 8192
#define D_IN   768
#define D_LAT  12288
#define K_TOP  64
#define K_CAND 96
#define TKBUF  2560

// ---------------- device scratch (no runtime allocation allowed) -----------
__device__ __half    g_Xh[(size_t)B_ROWS * D_IN];
__device__ __half    g_WhT[(size_t)D_LAT * D_IN];
__device__ float     g_WT[(size_t)D_LAT * D_IN];
__device__ uint16_t  g_Hk[(size_t)B_ROWS * D_LAT];   // bf16-format ordered keys
__device__ int       g_candi[(size_t)B_ROWS * K_CAND];

// ---------------- PTX helpers (compute_103-safe: no tcgen05) ---------------
__device__ __forceinline__ uint32_t smem_u32(const void* p) {
    uint32_t a;
    asm("{ .reg .u64 t; cvta.to.shared.u64 t, %1; cvt.u32.u64 %0, t; }" : "=r"(a) : "l"(p));
    return a;
}
#define CP_ASYNC16(dst, src) \
    asm volatile("cp.async.cg.shared.global [%0], [%1], 16;" :: "r"(dst), "l"(src))
#define CP_COMMIT() asm volatile("cp.async.commit_group;" ::: "memory")
#define CP_WAIT0()  asm volatile("cp.async.wait_group 0;" ::: "memory")

#define LDSM_X4(r0, r1, r2, r3, a) \
    asm volatile("ldmatrix.sync.aligned.m8n8.x4.shared.b16 {%0,%1,%2,%3}, [%4];" \
                 : "=r"(r0), "=r"(r1), "=r"(r2), "=r"(r3) : "r"(a))

// fp16 inputs, fp16 accumulator (half the acc registers of f32-acc)
__device__ __forceinline__ void mma16816_f16(uint32_t* c, const uint32_t* a, const uint32_t* b) {
    asm volatile(
        "mma.sync.aligned.m16n8k16.row.col.f16.f16.f16.f16 "
        "{%0,%1}, {%2,%3,%4,%5}, {%6,%7}, {%0,%1};"
        : "+r"(c[0]), "+r"(c[1])
        : "r"(a[0]), "r"(a[1]), "r"(a[2]), "r"(a[3]), "r"(b[0]), "r"(b[1]));
}

// monotonic bf16 -> u16 key (bigger float => bigger key). bf16 hi byte =
// sign+7exp -> few hot histogram buckets (the distribution topk is tuned for).
__device__ __forceinline__ uint16_t f2key16(float v) {
    uint16_t u = __bfloat16_as_ushort(__float2bfloat16(v));
    return (u & 0x8000) ? (uint16_t)~u : (uint16_t)(u | 0x8000);
}

// ---------------------------------------------------------------------------
// Prep kernels: X -> fp16 ; W_enc -> transposed fp32 + fp16 ; nop (profiling
// alignment: keeps the GEMM on the op index ncu captures).
// ---------------------------------------------------------------------------
__global__ void convert_x_kernel(const float* __restrict__ X) {
    const size_t n = (size_t)B_ROWS * D_IN / 2;
    const float2* X2 = reinterpret_cast<const float2*>(X);
    __half2* Y = reinterpret_cast<__half2*>(g_Xh);
    for (size_t i = (size_t)blockIdx.x * blockDim.x + threadIdx.x; i < n;
         i += (size_t)gridDim.x * blockDim.x) {
        float2 v = X2[i];
        Y[i] = __floats2half2_rn(v.x, v.y);
    }
}

__global__ void transpose_w_kernel(const float* __restrict__ W) {
    __shared__ float t[32][33];
    const int bx = blockIdx.x;  // over D_LAT/32
    const int by = blockIdx.y;  // over D_IN/32
    const int tx = threadIdx.x, ty = threadIdx.y;
    #pragma unroll
    for (int i = ty; i < 32; i += 8)
        t[i][tx] = W[(size_t)(by * 32 + i) * D_LAT + bx * 32 + tx];
    __syncthreads();
    #pragma unroll
    for (int i = ty; i < 32; i += 8) {
        float v = t[tx][i];
        size_t o = (size_t)(bx * 32 + i) * D_IN + by * 32 + tx;
        g_WT[o]  = v;
        g_WhT[o] = __float2half(v);
    }
}

__global__ void nop_kernel() {}

// ---------------------------------------------------------------------------
// Kernel: H ~= X @ W_enc + b_enc via fp16 mma.sync (f16 acc).
// CTA tile 128(M) x 256(N), 8 warps 2m x 4n -> warp tile 64x64.
// Bytes/MAC from smem: 2*(1/64+1/64) = 0.0625 (was 0.094 at 64x32).
// BK=64, 2-stage cp.async, rows padded to 144B (conflict-free ldmatrix).
// Epilogue: fp32 bias add, bf16-format ordered u16 keys.
// ---------------------------------------------------------------------------
#define BKC    64
#define NCH    (D_IN / BKC)          // 12
#define ROWB   144                   // 128B data + 16B pad
#define ATILE  (128 * ROWB)          // 18432 B
#define BTILE  (256 * ROWB)          // 36864 B
#define GEMM_DSMEM (2 * (ATILE + BTILE))   // 110592 B

__global__ __launch_bounds__(256, 2)
void gemm_enc_f16(const float* __restrict__ bias)
{
    extern __shared__ __align__(16) char sraw[];

    const uint32_t sbase = smem_u32(sraw);
    const int tid    = threadIdx.x;
    const int wid    = tid >> 5;
    const int lane   = tid & 31;
    const int warp_m = wid >> 2;          // 0..1 (64 rows each)
    const int warp_n = wid & 3;           // 0..3 (64 cols each)
    const int row0   = blockIdx.y * 128;
    const int col0   = blockIdx.x * 256;

    const char* Agl = reinterpret_cast<const char*>(g_Xh);
    const char* Bgl = reinterpret_cast<const char*>(g_WhT);

    // smem layout: [A0][A1][B0][B1]
    auto load_chunk = [&](int kc, int buf) {
        // A: 128 rows x 8 units = 1024 units -> 4 per thread
        #pragma unroll
        for (int t = 0; t < 4; t++) {
            int u   = tid + t * 256;
            int r   = u >> 3;
            int c16 = u & 7;
            uint32_t da = sbase + buf * ATILE + r * ROWB + c16 * 16;
            const char* sa = Agl + ((size_t)(row0 + r) * D_IN + kc * BKC) * 2 + c16 * 16;
            CP_ASYNC16(da, sa);
        }
        // B: 256 rows x 8 units = 2048 units -> 8 per thread
        #pragma unroll
        for (int t = 0; t < 8; t++) {
            int u   = tid + t * 256;
            int r   = u >> 3;
            int c16 = u & 7;
            uint32_t db = sbase + 2 * ATILE + buf * BTILE + r * ROWB + c16 * 16;
            const char* sb = Bgl + ((size_t)(col0 + r) * D_IN + kc * BKC) * 2 + c16 * 16;
            CP_ASYNC16(db, sb);
        }
    };

    uint32_t acc[4][8][2];               // f16x2 accumulators: 4 mi x 8 nj
    #pragma unroll
    for (int i = 0; i < 4; i++)
        #pragma unroll
        for (int j = 0; j < 8; j++) { acc[i][j][0] = 0u; acc[i][j][1] = 0u; }

    // A ldmatrix lane mapping (x4: 16x16 tile)
    const int a_row = warp_m * 64 + (lane & 15);
    const int a_col = (lane >> 4) * 8;                 // fp16 units
    // B ldmatrix x4 lane mapping: lane groups of 8 -> (nj parity, k half)
    const int bg  = lane >> 3;           // 0..3
    const int blr = lane & 7;
    const int b_rowx = warp_n * 64 + (bg >> 1) * 8 + blr;   // + pj*16
    const int b_colx = (bg & 1) * 8;                         // + ks*16

    load_chunk(0, 0);
    CP_COMMIT();
    CP_WAIT0();
    __syncthreads();

    for (int c = 0; c < NCH; c++) {
        const int buf = c & 1;
        if (c + 1 < NCH) {
            load_chunk(c + 1, buf ^ 1);
            CP_COMMIT();
        }

        const uint32_t sa = sbase + buf * ATILE;
        const uint32_t sb = sbase + 2 * ATILE + buf * BTILE;
        #pragma unroll
        for (int ks = 0; ks < 4; ks++) {
            uint32_t af[4][4], bfr[8][2];
            #pragma unroll
            for (int mi = 0; mi < 4; mi++) {
                uint32_t addr = sa + (a_row + mi * 16) * ROWB + (a_col + ks * 16) * 2;
                LDSM_X4(af[mi][0], af[mi][1], af[mi][2], af[mi][3], addr);
            }
            #pragma unroll
            for (int pj = 0; pj < 4; pj++) {
                uint32_t addr = sb + (b_rowx + pj * 16) * ROWB + (b_colx + ks * 16) * 2;
                LDSM_X4(bfr[2 * pj][0], bfr[2 * pj][1],
                        bfr[2 * pj + 1][0], bfr[2 * pj + 1][1], addr);
            }
            #pragma unroll
            for (int mi = 0; mi < 4; mi++)
                #pragma unroll
                for (int nj = 0; nj < 8; nj++)
                    mma16816_f16(acc[mi][nj], af[mi], bfr[nj]);
        }

        if (c + 1 < NCH) {
            CP_WAIT0();
            __syncthreads();
        }
    }

    // epilogue: fp32 bias add, bf16-format ordered u16 keys, packed stores
    const int er = lane >> 2;          // 0..7
    const int ec = (lane & 3) * 2;     // 0,2,4,6
    #pragma unroll
    for (int mi = 0; mi < 4; mi++) {
        #pragma unroll
        for (int nj = 0; nj < 8; nj++) {
            const int r  = row0 + warp_m * 64 + mi * 16 + er;
            const int cc = col0 + warp_n * 64 + nj * 8 + ec;
            const float bx = bias[cc], by = bias[cc + 1];
            __half2 h0 = *reinterpret_cast<__half2*>(&acc[mi][nj][0]);
            __half2 h1 = *reinterpret_cast<__half2*>(&acc[mi][nj][1]);
            uint32_t p0 = (uint32_t)f2key16(__low2float(h0) + bx) |
                          ((uint32_t)f2key16(__high2float(h0) + by) << 16);
            uint32_t p1 = (uint32_t)f2key16(__low2float(h1) + bx) |
                          ((uint32_t)f2key16(__high2float(h1) + by) << 16);
            *reinterpret_cast<uint32_t*>(g_Hk + (size_t)r * D_LAT + cc) = p0;
            *reinterpret_cast<uint32_t*>(g_Hk + (size_t)(r + 8) * D_LAT + cc) = p1;
        }
    }
}

// ---------------------------------------------------------------------------
// Kernel: per-row top-96 candidate indices from u16 keys. (R8/R9 structure,
// bf16-format keys -> few hot hi-byte buckets.)
// ---------------------------------------------------------------------------
__device__ __forceinline__ void hadd(int* hist, int bucket) {
    unsigned m = __match_any_sync(0xffffffffu, bucket);
    if ((threadIdx.x & 31) == __ffs(m) - 1)
        atomicAdd(&hist[bucket], __popc(m));
}

__global__ __launch_bounds__(256)
void topk_kernel()
{
    __shared__ __align__(16) uint32_t skeys[D_LAT / 2];   // 24 KB
    __shared__ int hist[256];
    __shared__ uint32_t buf[TKBUF];                        // (key16<<16)|idx
    __shared__ int s_d1, s_rem1, s_e, s_rem2, s_cnt, s_eq, s_bcnt;

    const int row = blockIdx.x;
    const int tid = threadIdx.x;

    hist[tid] = 0;
    if (tid == 0) { s_cnt = 0; s_eq = 0; s_bcnt = 0; }
    __syncthreads();

    // sweep 1: load -> stage + pass-1 histogram of high bytes (convergent)
    const uint4* src = reinterpret_cast<const uint4*>(g_Hk + (size_t)row * D_LAT);
    uint4* dst = reinterpret_cast<uint4*>(skeys);
    #pragma unroll
    for (int j = 0; j < 6; j++) {
        uint4 v = src[tid + 256 * j];
        dst[tid + 256 * j] = v;
        hadd(hist, (int)((v.x >> 8) & 0xFF));  hadd(hist, (int)(v.x >> 24));
        hadd(hist, (int)((v.y >> 8) & 0xFF));  hadd(hist, (int)(v.y >> 24));
        hadd(hist, (int)((v.z >> 8) & 0xFF));  hadd(hist, (int)(v.z >> 24));
        hadd(hist, (int)((v.w >> 8) & 0xFF));  hadd(hist, (int)(v.w >> 24));
    }
    __syncthreads();
    if (tid == 0) {
        int cum = 0, d = 255;
        for (; d > 0; d--) {
            if (cum + hist[d] >= K_CAND) break;
            cum += hist[d];
        }
        s_d1 = d;
        s_rem1 = K_CAND - cum;
    }
    __syncthreads();
    const int d1 = s_d1, rem1 = s_rem1;
    hist[tid] = 0;
    __syncthreads();

    // sweep 2: classify. definite candidates out; threshold bucket -> buffer
    int* cand = g_candi + (size_t)row * K_CAND;
    #pragma unroll 4
    for (int i = tid; i < D_LAT / 2; i += 256) {
        uint32_t w = skeys[i];
        uint32_t k0 = w & 0xFFFFu, k1 = w >> 16;
        int hb0 = (int)(k0 >> 8), hb1 = (int)(k1 >> 8);
        if (hb0 > d1)       cand[atomicAdd(&s_cnt, 1)] = 2 * i;
        else if (hb0 == d1) {
            int p = atomicAdd(&s_bcnt, 1);
            if (p < TKBUF) buf[p] = (k0 << 16) | (uint32_t)(2 * i);
        }
        if (hb1 > d1)       cand[atomicAdd(&s_cnt, 1)] = 2 * i + 1;
        else if (hb1 == d1) {
            int p = atomicAdd(&s_bcnt, 1);
            if (p < TKBUF) buf[p] = (k1 << 16) | (uint32_t)(2 * i + 1);
        }
    }
    __syncthreads();
    const int bn = s_bcnt;

    if (bn <= TKBUF) {
        for (int i = tid; i < bn; i += 256)
            atomicAdd(&hist[(buf[i] >> 16) & 0xFF], 1);
        __syncthreads();
        if (tid == 0) {
            int cum = 0, e = 255;
            for (; e > 0; e--) {
                if (cum + hist[e] >= rem1) break;
                cum += hist[e];
            }
            s_e = e;
            s_rem2 = rem1 - cum;
        }
        __syncthreads();
        const int e = s_e, rem2 = s_rem2;
        for (int i = tid; i < bn; i += 256) {
            uint32_t w  = buf[i];
            int lb = (int)((w >> 16) & 0xFF);
            if (lb > e)        cand[atomicAdd(&s_cnt, 1)] = (int)(w & 0xFFFFu);
            else if (lb == e && atomicAdd(&s_eq, 1) < rem2)
                               cand[atomicAdd(&s_cnt, 1)] = (int)(w & 0xFFFFu);
        }
    } else {
        // exact fallback (data-independent correctness)
        #pragma unroll 4
        for (int i = tid; i < D_LAT / 2; i += 256) {
            uint32_t w = skeys[i];
            uint32_t k0 = w & 0xFFFFu, k1 = w >> 16;
            if ((int)(k0 >> 8) == d1) atomicAdd(&hist[k0 & 0xFF], 1);
            if ((int)(k1 >> 8) == d1) atomicAdd(&hist[k1 & 0xFF], 1);
        }
        __syncthreads();
        if (tid == 0) {
            int cum = 0, e = 255;
            for (; e > 0; e--) {
                if (cum + hist[e] >= rem1) break;
                cum += hist[e];
            }
            s_e = e;
            s_rem2 = rem1 - cum;
        }
        __syncthreads();
        const int e = s_e, rem2 = s_rem2;
        #pragma unroll 4
        for (int i = tid; i < D_LAT / 2; i += 256) {
            uint32_t w = skeys[i];
            uint32_t k0 = w & 0xFFFFu, k1 = w >> 16;
            if ((int)(k0 >> 8) == d1) {
                int lb = (int)(k0 & 0xFF);
                if (lb > e)        cand[atomicAdd(&s_cnt, 1)] = 2 * i;
                else if (lb == e && atomicAdd(&s_eq, 1) < rem2)
                                   cand[atomicAdd(&s_cnt, 1)] = 2 * i;
            }
            if ((int)(k1 >> 8) == d1) {
                int lb = (int)(k1 & 0xFF);
                if (lb > e)        cand[atomicAdd(&s_cnt, 1)] = 2 * i + 1;
                else if (lb == e && atomicAdd(&s_eq, 1) < rem2)
                                   cand[atomicAdd(&s_cnt, 1)] = 2 * i + 1;
            }
        }
    }
}

// ---------------------------------------------------------------------------
// Kernel: fused exact recompute (fp32) of the 96 candidates + exact top-64
// (jax tie semantics: value desc, index asc) + z scatter + sparse decode.
// ---------------------------------------------------------------------------
__global__ __launch_bounds__(256)
void recon_kernel(const float* __restrict__ X, const float* __restrict__ b_enc,
                  const float* __restrict__ Wdec, const float* __restrict__ bdec,
                  float* __restrict__ z, float* __restrict__ recon)
{
    __shared__ __align__(16) float xs[D_IN];
    __shared__ int   ci[K_CAND];
    __shared__ float cv[K_CAND];
    __shared__ float sv[K_TOP];
    __shared__ int   si[K_TOP];

    const int row = blockIdx.x;
    const int tid = threadIdx.x;
    const int wid = tid >> 5, lane = tid & 31;

    {
        const float4* X4 = reinterpret_cast<const float4*>(X + (size_t)row * D_IN);
        float4* xs4 = reinterpret_cast<float4*>(xs);
        if (tid < D_IN / 4) xs4[tid] = X4[tid];
    }
    if (tid < K_CAND)
        ci[tid] = g_candi[(size_t)row * K_CAND + tid];
    __syncthreads();

    const float4* xs4 = reinterpret_cast<const float4*>(xs);
    for (int c = wid; c < K_CAND; c += 8) {
        const float4* wr = reinterpret_cast<const float4*>(g_WT + (size_t)ci[c] * D_IN);
        float s = 0.f;
        #pragma unroll
        for (int j = 0; j < D_IN / 128; j++) {
            float4 a = xs4[lane + 32 * j];
            float4 b = wr[lane + 32 * j];
            s = fmaf(a.x, b.x, s); s = fmaf(a.y, b.y, s);
            s = fmaf(a.z, b.z, s); s = fmaf(a.w, b.w, s);
        }
        #pragma unroll
        for (int o = 16; o; o >>= 1) s += __shfl_xor_sync(0xffffffff, s, o);
        if (lane == 0) cv[c] = s + b_enc[ci[c]];
    }
    __syncthreads();

    if (tid < K_CAND) {
        const float v  = cv[tid];
        const int   id = ci[tid];
        int r = 0;
        #pragma unroll 8
        for (int j = 0; j < K_CAND; j++) {
            float vj = cv[j];
            r += (vj > v) || (vj == v && ci[j] < id);
        }
        if (r < K_TOP) {
            z[(size_t)row * D_LAT + id] = v;
            sv[r] = v;
            si[r] = id;
        }
    }
    __syncthreads();

    if (tid < D_IN / 4) {
        const float4* W4 = reinterpret_cast<const float4*>(Wdec);
        float4 acc = reinterpret_cast<const float4*>(bdec)[tid];
        #pragma unroll 4
        for (int j = 0; j < K_TOP; j++) {
            float4 w = W4[(size_t)si[j] * (D_IN / 4) + tid];
            float v  = sv[j];
            acc.x = fmaf(v, w.x, acc.x);
            acc.y = fmaf(v, w.y, acc.y);
            acc.z = fmaf(v, w.z, acc.z);
            acc.w = fmaf(v, w.w, acc.w);
        }
        reinterpret_cast<float4*>(recon)[(size_t)row * (D_IN / 4) + tid] = acc;
    }
}

// ---------------------------------------------------------------------------
extern "C" void kernel_launch(void* const* d_in, const int* in_sizes, int n_in,
                              void* d_out, int out_size)
{
    const float* x     = (const float*)d_in[0];
    const float* W_enc = (const float*)d_in[1];
    const float* b_enc = (const float*)d_in[2];
    const float* W_dec = (const float*)d_in[3];
    const float* b_dec = (const float*)d_in[4];

    float* out   = (float*)d_out;
    float* recon = out;                              // [B_ROWS, D_IN]
    float* z     = out + (size_t)B_ROWS * D_IN;      // [B_ROWS, D_LAT]

    cudaFuncSetAttribute(gemm_enc_f16, cudaFuncAttributeMaxDynamicSharedMemorySize,
                         GEMM_DSMEM);

    cudaMemsetAsync(z, 0, (size_t)B_ROWS * D_LAT * sizeof(float));

    convert_x_kernel<<<2048, 256>>>(x);
    transpose_w_kernel<<<dim3(D_LAT / 32, D_IN / 32), dim3(32, 8)>>>(W_enc);

    nop_kernel<<<1, 32>>>();   // keeps GEMM on ncu's captured op index

    gemm_enc_f16<<<dim3(D_LAT / 256, B_ROWS / 128), 256, GEMM_DSMEM>>>(b_enc);

    topk_kernel<<<B_ROWS, 256>>>();
    recon_kernel<<<B_ROWS, 256>>>(x, b_enc, W_dec, b_dec, z, recon);
}